// round 4
// baseline (speedup 1.0000x reference)
#include <cuda_runtime.h>
#include <cstdint>
#include <cmath>

// ---------------------------------------------------------------------------
// WeightedRankNet, single-wave fused kernel:
//  - each thread: 4 gathered elements (regs) + ~4 col16 rows, loads interleaved
//  - deterministic grid reduction for avg (arrival counter, fixed-order fold)
//  - spin on flag (all blocks co-resident), combine, store float4
// Threefry-2x32-20, key=(0,1), partitionable: bits = out0 ^ out1.
// ---------------------------------------------------------------------------

#define N_FEAT        136
#define COL_DOCLEN    14
#define COL_WHOLE_LEN 16
#define COL_TF        24
#define COL_INLINK    127
#define COL_OUTLINK   128
#define COL_PAGERANK  129

#define TPB   256
#define MAXB  2048

__device__ float          g_partials[MAXB];
__device__ volatile float g_avg;
__device__ int            g_counter;
__device__ volatile int   g_flag;

// ---- init: reset sync state so the graph is replayable ----------------------
__global__ void init_kernel() {
    g_counter = 0;
    g_flag = 0;
}

// ---- Threefry-2x32 -----------------------------------------------------------
__device__ __forceinline__ uint32_t rotl32(uint32_t x, uint32_t r) {
    return __funnelshift_l(x, x, r);
}

__device__ __forceinline__ uint32_t threefry_bits(uint32_t ctr) {
    uint32_t x0 = 0u;
    uint32_t x1 = ctr;
    const uint32_t ks0 = 0u, ks1 = 1u, ks2 = 0x1BD11BDBu;
    x0 += ks0; x1 += ks1;
#define TF_R(r) { x0 += x1; x1 = rotl32(x1, (r)); x1 ^= x0; }
    TF_R(13) TF_R(15) TF_R(26) TF_R(6)
    x0 += ks1; x1 += ks2 + 1u;
    TF_R(17) TF_R(29) TF_R(16) TF_R(24)
    x0 += ks2; x1 += ks0 + 2u;
    TF_R(13) TF_R(15) TF_R(26) TF_R(6)
    x0 += ks0; x1 += ks1 + 3u;
    TF_R(17) TF_R(29) TF_R(16) TF_R(24)
    x0 += ks1; x1 += ks2 + 4u;
    TF_R(13) TF_R(15) TF_R(26) TF_R(6)
    x0 += ks2; x1 += ks0 + 5u;
#undef TF_R
    return x0 ^ x1;
}

// ---- main fused kernel --------------------------------------------------------
__global__ void __launch_bounds__(TPB, 7)
fused_kernel(const int* __restrict__ idxs,
             const float* __restrict__ gf,
             const float* __restrict__ s_k1,
             const float* __restrict__ s_b,
             const float* __restrict__ s_bw,
             const float* __restrict__ s_pr,
             const float* __restrict__ s_in,
             const float* __restrict__ s_out,
             const float* __restrict__ s_fr,
             float* __restrict__ out,
             int batch, int n_docs, float idf, int nblocks)
{
    const int tid      = blockIdx.x * blockDim.x + threadIdx.x;
    const int nthreads = nblocks * TPB;
    const int base     = tid * 4;

    // ---- issue ALL loads first: 1 idx + up to 16 gather + ~4 col16 ----
    int idx0 = 0, idx1 = 0, idx2 = 0, idx3 = 0;
    if (base + 3 < batch) {
        int4 iv = *reinterpret_cast<const int4*>(idxs + base);
        idx0 = iv.x; idx1 = iv.y; idx2 = iv.z; idx3 = iv.w;
    } else if (base < batch) {
        idx0 = idxs[base];
        idx1 = (base + 1 < batch) ? idxs[base + 1] : idx0;
        idx2 = (base + 2 < batch) ? idxs[base + 2] : idx0;
        idx3 = (base + 3 < batch) ? idxs[base + 3] : idx0;
    }

    float dl[4], tf[4], inl[4], oul[4], pr[4];
    {
        const int ids[4] = {idx0, idx1, idx2, idx3};
        #pragma unroll
        for (int k = 0; k < 4; k++) {
            long long row = (long long)ids[k] * (long long)N_FEAT;
            dl[k]  = __ldg(gf + row + COL_DOCLEN);
            tf[k]  = __ldg(gf + row + COL_TF);
            inl[k] = __ldg(gf + row + COL_INLINK);
            float2 op = __ldg(reinterpret_cast<const float2*>(gf + row + COL_OUTLINK));
            oul[k] = op.x; pr[k] = op.y;
        }
    }

    // col16 strided loads interleave with the gather latency
    float csum = 0.0f;
    for (long long i = tid; i < n_docs; i += nthreads)
        csum += __ldg(gf + i * N_FEAT + COL_WHOLE_LEN);

    // ---- avg-independent compute ----
    const float k1  = __ldg(s_k1);
    const float b   = __ldg(s_b);
    const float bw  = __ldg(s_bw);
    const float prw = __ldg(s_pr);
    const float inw = __ldg(s_in);
    const float otw = __ldg(s_out);
    const float frw = __ldg(s_fr);

    float A[4], D[4], E[4], P[4];
    #pragma unroll
    for (int k = 0; k < 4; k++) {
        uint32_t bits = threefry_bits((uint32_t)(base + k));
        float u = __uint_as_float((bits >> 9) | 0x3f800000u) - 1.0f;
        u = fmaxf(0.0f, u);
        P[k] = prw * pr[k] + inw * inl[k] + otw * oul[k] + u * frw;
        A[k] = bw * idf * (tf[k] * (k1 + 1.0f));
        D[k] = tf[k] + k1 * (1.0f - b);
        E[k] = k1 * b * dl[k];
    }

    // ---- block reduction of col16 partial ----
    __shared__ float sd[TPB];
    sd[threadIdx.x] = csum;
    __syncthreads();
    for (int k = TPB / 2; k > 0; k >>= 1) {
        if (threadIdx.x < k) sd[threadIdx.x] += sd[threadIdx.x + k];
        __syncthreads();
    }
    if (threadIdx.x == 0) {
        g_partials[blockIdx.x] = sd[0];
        __threadfence();
        int old = atomicAdd(&g_counter, 1);
        if (old == nblocks - 1) {
            // last block: deterministic fixed-order fold
            float t = 0.0f;
            for (int i = 0; i < nblocks; i++) t += g_partials[i];
            g_avg = t / (float)n_docs;
            __threadfence();
            g_flag = 1;
        }
    }

    // ---- spin until avg is published ----
    if (threadIdx.x == 0) {
        while (g_flag == 0) { __nanosleep(128); }
    }
    __syncthreads();
    const float avg = g_avg;

    // ---- combine + store ----
    if (base + 3 < batch) {
        float4 o;
        o.x = P[0] + A[0] / (D[0] + E[0] / avg);
        o.y = P[1] + A[1] / (D[1] + E[1] / avg);
        o.z = P[2] + A[2] / (D[2] + E[2] / avg);
        o.w = P[3] + A[3] / (D[3] + E[3] / avg);
        *reinterpret_cast<float4*>(out + base) = o;
    } else {
        #pragma unroll
        for (int k = 0; k < 4; k++) {
            if (base + k < batch)
                out[base + k] = P[k] + A[k] / (D[k] + E[k] / avg);
        }
    }
}

// ---------------------------------------------------------------------------
extern "C" void kernel_launch(void* const* d_in, const int* in_sizes, int n_in,
                              void* d_out, int out_size)
{
    const int*   idxs = (const int*)d_in[0];
    const float* gf   = (const float*)d_in[1];
    const float* k1   = (const float*)d_in[2];
    const float* b    = (const float*)d_in[3];
    const float* bw   = (const float*)d_in[4];
    const float* prw  = (const float*)d_in[5];
    const float* inw  = (const float*)d_in[6];
    const float* outw = (const float*)d_in[7];
    const float* frw  = (const float*)d_in[8];
    float* out = (float*)d_out;

    int batch  = in_sizes[0];
    int n_docs = in_sizes[1] / N_FEAT;

    // idf in the reference's exact f32 operation order (num == total):
    float total = (float)n_docs;
    float idf = logf(((total - total) + 0.5f) / (total + 0.5f) + 1.0f);

    int nblocks = (batch + TPB * 4 - 1) / (TPB * 4);
    // Deadlock safety: all blocks must be co-resident. __launch_bounds__(256,7)
    // guarantees 7 blocks/SM * 148 SMs = 1036 slots; 977 blocks fit.
    if (nblocks > 1036) nblocks = 1036;  // (not hit for batch = 1e6)

    init_kernel<<<1, 1>>>();
    fused_kernel<<<nblocks, TPB>>>(idxs, gf, k1, b, bw, prw, inw, outw, frw,
                                   out, batch, n_docs, idf, nblocks);
}